// round 2
// baseline (speedup 1.0000x reference)
#include <cuda_runtime.h>
#include <cuda_bf16.h>
#include <stdint.h>

// ---------------- problem constants (static shapes) ----------------
#define N_OV 20000      // original vertices
#define N_OF 30000      // original faces
#define N_SV 4000       // simplified vertices
#define N_SF 5000       // simplified faces
#define NSAMP 50
#define N_SAMPLES 250000        // N_SF * NSAMP
#define REV_BLOCKS 490          // 490 * 512 = 250880 padded samples
#define N_SAMPLES_PAD 250880
#define FWD_CHUNK 3000          // 10 chunks of original barycenters
#define REV_TILE 2500           // 8 tiles of original vertices

// ---------------- device scratch (static, no runtime alloc) ----------------
__device__ float4   g_tv[N_OV];          // (-2x,-2y,-2z, |v|^2) original verts
__device__ float4   g_ob[N_OF];          // (-2bx,-2by,-2bz, |b|^2) original barycenters
__device__ float4   g_sb[N_SF];          // (bx,by,bz, |b|^2) simplified barycenters
__device__ unsigned g_minfwd[N_SF];      // min d2 bits (atomicMin)
__device__ float4   g_samples[N_SAMPLES_PAD]; // (x,y,z, |p|^2)
__device__ float    g_dist[N_SAMPLES_PAD];
__device__ unsigned g_maxbits;

// ---------------- threefry2x32 (JAX-exact, 20 rounds) ----------------
__device__ __forceinline__ uint32_t rotl32(uint32_t x, int r) {
    return (x << r) | (x >> (32 - r));
}

__device__ __forceinline__ void threefry2x32(uint32_t k0, uint32_t k1,
                                             uint32_t x0, uint32_t x1,
                                             uint32_t& o0, uint32_t& o1) {
    uint32_t ks0 = k0, ks1 = k1, ks2 = k0 ^ k1 ^ 0x1BD11BDAu;
    x0 += ks0; x1 += ks1;
    // rounds 1-4 (rot set A), keyschedule i=1
    x0 += x1; x1 = rotl32(x1, 13); x1 ^= x0;
    x0 += x1; x1 = rotl32(x1, 15); x1 ^= x0;
    x0 += x1; x1 = rotl32(x1, 26); x1 ^= x0;
    x0 += x1; x1 = rotl32(x1,  6); x1 ^= x0;
    x0 += ks1; x1 += ks2 + 1u;
    // rounds 5-8 (rot set B), keyschedule i=2
    x0 += x1; x1 = rotl32(x1, 17); x1 ^= x0;
    x0 += x1; x1 = rotl32(x1, 29); x1 ^= x0;
    x0 += x1; x1 = rotl32(x1, 16); x1 ^= x0;
    x0 += x1; x1 = rotl32(x1, 24); x1 ^= x0;
    x0 += ks2; x1 += ks0 + 2u;
    // rounds 9-12 (rot set A), keyschedule i=3
    x0 += x1; x1 = rotl32(x1, 13); x1 ^= x0;
    x0 += x1; x1 = rotl32(x1, 15); x1 ^= x0;
    x0 += x1; x1 = rotl32(x1, 26); x1 ^= x0;
    x0 += x1; x1 = rotl32(x1,  6); x1 ^= x0;
    x0 += ks0; x1 += ks1 + 3u;
    // rounds 13-16 (rot set B), keyschedule i=4
    x0 += x1; x1 = rotl32(x1, 17); x1 ^= x0;
    x0 += x1; x1 = rotl32(x1, 29); x1 ^= x0;
    x0 += x1; x1 = rotl32(x1, 16); x1 ^= x0;
    x0 += x1; x1 = rotl32(x1, 24); x1 ^= x0;
    x0 += ks1; x1 += ks2 + 4u;
    // rounds 17-20 (rot set A), keyschedule i=5
    x0 += x1; x1 = rotl32(x1, 13); x1 ^= x0;
    x0 += x1; x1 = rotl32(x1, 15); x1 ^= x0;
    x0 += x1; x1 = rotl32(x1, 26); x1 ^= x0;
    x0 += x1; x1 = rotl32(x1,  6); x1 ^= x0;
    x0 += ks2; x1 += ks0 + 5u;
    o0 = x0; o1 = x1;
}

__device__ __forceinline__ float bits_to_uniform(uint32_t bits) {
    // JAX: bitcast((bits >> 9) | 0x3f800000) - 1.0  -> [0,1)
    return __uint_as_float((bits >> 9) | 0x3f800000u) - 1.0f;
}

// ---------------- kernel A: prep (tv, barycenters, resets) ----------------
__global__ void prep_kernel(const float* __restrict__ ov,
                            const int*   __restrict__ of,
                            const float* __restrict__ sv,
                            const int*   __restrict__ sf) {
    int i = blockIdx.x * 256 + threadIdx.x;
    if (i < N_OV) {
        float x = ov[3 * i], y = ov[3 * i + 1], z = ov[3 * i + 2];
        g_tv[i] = make_float4(-2.0f * x, -2.0f * y, -2.0f * z,
                              x * x + y * y + z * z);
    }
    if (i < N_OF) {
        int f0 = of[3 * i], f1 = of[3 * i + 1], f2 = of[3 * i + 2];
        float bx = (ov[3 * f0] + ov[3 * f1] + ov[3 * f2]) / 3.0f;
        float by = (ov[3 * f0 + 1] + ov[3 * f1 + 1] + ov[3 * f2 + 1]) / 3.0f;
        float bz = (ov[3 * f0 + 2] + ov[3 * f1 + 2] + ov[3 * f2 + 2]) / 3.0f;
        g_ob[i] = make_float4(-2.0f * bx, -2.0f * by, -2.0f * bz,
                              bx * bx + by * by + bz * bz);
    }
    if (i < N_SF) {
        int f0 = sf[3 * i], f1 = sf[3 * i + 1], f2 = sf[3 * i + 2];
        float bx = (sv[3 * f0] + sv[3 * f1] + sv[3 * f2]) / 3.0f;
        float by = (sv[3 * f0 + 1] + sv[3 * f1 + 1] + sv[3 * f2 + 1]) / 3.0f;
        float bz = (sv[3 * f0 + 2] + sv[3 * f1 + 2] + sv[3 * f2 + 2]) / 3.0f;
        g_sb[i] = make_float4(bx, by, bz, bx * bx + by * by + bz * bz);
        g_minfwd[i] = 0x7f800000u;  // +inf
    }
    if (i == 0) g_maxbits = 0u;
}

// ---------------- kernel B: forward min (brute force, chunked) ----------------
__global__ void __launch_bounds__(128) forward_kernel() {
    __shared__ float4 sob[FWD_CHUNK];
    int tid = threadIdx.x;
    int q = blockIdx.x * 128 + tid;
    int cbase = blockIdx.y * FWD_CHUNK;
    for (int k = tid; k < FWD_CHUNK; k += 128) sob[k] = g_ob[cbase + k];
    __syncthreads();
    if (q < N_SF) {
        float4 Q = g_sb[q];
        float m = 3.0e38f;
#pragma unroll 5
        for (int k = 0; k < FWD_CHUNK; k++) {
            float4 v = sob[k];
            float t = fmaf(v.x, Q.x, fmaf(v.y, Q.y, fmaf(v.z, Q.z, v.w)));
            m = fminf(m, t);
        }
        float d2 = fmaxf(m + Q.w, 0.0f);
        atomicMin(&g_minfwd[q], __float_as_uint(d2));
    }
}

// ---------------- kernel C: sample generation (partitionable threefry) ------
// JAX with jax_threefry_partitionable=True (modern default):
//   split(key,2): rk_i = threefry2x32(key, (0, i))  [fold_in]
//   random_bits(key, 32, n): per element i (uint64 counter, hi=0 here),
//     (b1,b2) = threefry2x32(key, (hi32(i), lo32(i))); bits = b1 ^ b2
__device__ __forceinline__ float4 make_sample(int s, uint32_t bits_u1, uint32_t bits_r2,
                                              const float* __restrict__ sv,
                                              const int*   __restrict__ sf) {
    float u1 = bits_to_uniform(bits_u1);
    float r2 = bits_to_uniform(bits_r2);
    float sq = sqrtf(u1);
    float a = 1.0f - sq;
    float b = sq * (1.0f - r2);
    float c = sq * r2;
    int f = s / NSAMP;
    int i0 = sf[3 * f], i1 = sf[3 * f + 1], i2 = sf[3 * f + 2];
    float x = a * sv[3 * i0]     + b * sv[3 * i1]     + c * sv[3 * i2];
    float y = a * sv[3 * i0 + 1] + b * sv[3 * i1 + 1] + c * sv[3 * i2 + 1];
    float z = a * sv[3 * i0 + 2] + b * sv[3 * i1 + 2] + c * sv[3 * i2 + 2];
    return make_float4(x, y, z, x * x + y * y + z * z);
}

__global__ void gen_samples_kernel(const float* __restrict__ sv,
                                   const int*   __restrict__ sf) {
    int j = blockIdx.x * 256 + threadIdx.x;
    if (j >= N_SAMPLES_PAD) return;

    // fold_in-derived subkeys from key(42) = (0, 42)
    uint32_t rk1_0, rk1_1, rk2_0, rk2_1;
    threefry2x32(0u, 42u, 0u, 0u, rk1_0, rk1_1);  // rk1 = fold_in(key, 0)
    threefry2x32(0u, 42u, 0u, 1u, rk2_0, rk2_1);  // rk2 = fold_in(key, 1)

    // padding entries clone sample 0 (cannot change max; ignored in sums)
    int s = (j < N_SAMPLES) ? j : 0;

    uint32_t a0, a1, b0, b1;
    threefry2x32(rk1_0, rk1_1, 0u, (uint32_t)s, a0, a1);
    threefry2x32(rk2_0, rk2_1, 0u, (uint32_t)s, b0, b1);
    g_samples[j] = make_sample(s, a0 ^ a1, b0 ^ b1, sv, sf);
}

// ---------------- kernel D: reverse 1-NN (dominant) ----------------
__global__ void __launch_bounds__(128) reverse_kernel() {
    __shared__ float4 sv[REV_TILE];
    int tid = threadIdx.x;
    int base = blockIdx.x * 512;

    float px[4], py[4], pz[4], m[4];
#pragma unroll
    for (int u = 0; u < 4; u++) {
        float4 s = g_samples[base + u * 128 + tid];
        px[u] = s.x; py[u] = s.y; pz[u] = s.z;
        m[u] = 3.0e38f;
    }

    for (int t0 = 0; t0 < N_OV; t0 += REV_TILE) {
        __syncthreads();
        for (int k = tid; k < REV_TILE; k += 128) sv[k] = g_tv[t0 + k];
        __syncthreads();
#pragma unroll 4
        for (int k = 0; k < REV_TILE; k++) {
            float4 v = sv[k];
#pragma unroll
            for (int u = 0; u < 4; u++) {
                float t = fmaf(v.x, px[u], fmaf(v.y, py[u], fmaf(v.z, pz[u], v.w)));
                m[u] = fminf(m[u], t);
            }
        }
    }

    float lmax = 0.0f;
#pragma unroll
    for (int u = 0; u < 4; u++) {
        int s = base + u * 128 + tid;
        float pp = g_samples[s].w;
        float d = sqrtf(fmaxf(m[u] + pp, 0.0f));
        g_dist[s] = d;
        lmax = fmaxf(lmax, d);
    }

    __shared__ float red[128];
    red[tid] = lmax;
    __syncthreads();
#pragma unroll
    for (int o = 64; o > 0; o >>= 1) {
        if (tid < o) red[tid] = fmaxf(red[tid], red[tid + o]);
        __syncthreads();
    }
    if (tid == 0) atomicMax(&g_maxbits, __float_as_uint(red[0]));
}

// ---------------- kernel E: deterministic final reduction ----------------
__global__ void __launch_bounds__(512) final_kernel(const float* __restrict__ fp,
                                                    float* __restrict__ out) {
    __shared__ double red[512];
    int tid = threadIdx.x;

    double fwd = 0.0, pen = 0.0, rev = 0.0;
    for (int i = tid; i < N_SF; i += 512) {
        float p = fp[i];
        float d2 = __uint_as_float(g_minfwd[i]);
        fwd += (double)(p * sqrtf(d2));
        pen += (double)(1.0f - p);
    }
    for (int s = tid; s < N_SAMPLES; s += 512) {
        rev += (double)(fp[s / NSAMP] * g_dist[s]);
    }

    double totF, totP, totR;
    red[tid] = fwd; __syncthreads();
    for (int o = 256; o > 0; o >>= 1) { if (tid < o) red[tid] += red[tid + o]; __syncthreads(); }
    totF = red[0]; __syncthreads();
    red[tid] = pen; __syncthreads();
    for (int o = 256; o > 0; o >>= 1) { if (tid < o) red[tid] += red[tid + o]; __syncthreads(); }
    totP = red[0]; __syncthreads();
    red[tid] = rev; __syncthreads();
    for (int o = 256; o > 0; o >>= 1) { if (tid < o) red[tid] += red[tid + o]; __syncthreads(); }
    totR = red[0];

    if (tid == 0) {
        double maxd = (double)__uint_as_float(g_maxbits);
        double result = totF + 1e-4 * totP + totR / (maxd + 1e-8) * 0.1;
        out[0] = (float)result;
    }
}

// ---------------- launch ----------------
extern "C" void kernel_launch(void* const* d_in, const int* in_sizes, int n_in,
                              void* d_out, int out_size) {
    const float* ov = (const float*)d_in[0];  // original_vertices [20000,3]
    const int*   of = (const int*)  d_in[1];  // original_faces    [30000,3]
    const float* sv = (const float*)d_in[2];  // simplified_vertices [4000,3]
    const int*   sf = (const int*)  d_in[3];  // simplified_faces  [5000,3]
    const float* fp = (const float*)d_in[4];  // face_probabilities [5000]
    float* out = (float*)d_out;

    prep_kernel<<<(N_OF + 255) / 256, 256>>>(ov, of, sv, sf);
    gen_samples_kernel<<<(N_SAMPLES_PAD + 255) / 256, 256>>>(sv, sf);
    {
        dim3 grid((N_SF + 127) / 128, N_OF / FWD_CHUNK);
        forward_kernel<<<grid, 128>>>();
    }
    reverse_kernel<<<REV_BLOCKS, 128>>>();
    final_kernel<<<1, 512>>>(fp, out);
}

// round 3
// speedup vs baseline: 1.1475x; 1.1475x over previous
#include <cuda_runtime.h>
#include <cuda_bf16.h>
#include <stdint.h>

// ---------------- problem constants (static shapes) ----------------
#define N_OV 20000      // original vertices
#define N_OF 30000      // original faces
#define N_SV 4000       // simplified vertices
#define N_SF 5000       // simplified faces
#define NSAMP 50
#define N_SAMPLES 250000        // N_SF * NSAMP
#define REV_BLOCKS 245          // 245 * 1024 = 250880 padded samples
#define N_SAMPLES_PAD 250880
#define FWD_CHUNK 3000          // 10 chunks of original barycenters
#define REV_TILE 2000           // 10 tiles of original vertices

// ---------------- device scratch (static, no runtime alloc) ----------------
__device__ float4        g_tv[N_OV];        // (-2x,-2y,-2z,|v|^2) (forward-style use)
__device__ ulonglong2    g_tv2[2 * N_OV];   // duplicated-lane pairs: [2i]=(vx2,vy2) [2i+1]=(vz2,vw2)
__device__ float4        g_ob[N_OF];        // (-2bx,-2by,-2bz, |b|^2) original barycenters
__device__ float4        g_sb[N_SF];        // (bx,by,bz, |b|^2) simplified barycenters
__device__ unsigned      g_minfwd[N_SF];    // min d2 bits (atomicMin)
__device__ float4        g_samples[N_SAMPLES_PAD]; // (x,y,z, |p|^2)
__device__ float         g_dist[N_SAMPLES_PAD];
__device__ unsigned      g_maxbits;

// ---------------- packed f32x2 helpers ----------------
__device__ __forceinline__ long long pack2(float a, float b) {
    long long r;
    asm("mov.b64 %0, {%1, %2};" : "=l"(r) : "f"(a), "f"(b));
    return r;
}
__device__ __forceinline__ long long fma2(long long a, long long b, long long c) {
    long long d;
    asm("fma.rn.f32x2 %0, %1, %2, %3;" : "=l"(d) : "l"(a), "l"(b), "l"(c));
    return d;
}
__device__ __forceinline__ void unpack2(long long v, float& lo, float& hi) {
    asm("mov.b64 {%0, %1}, %2;" : "=f"(lo), "=f"(hi) : "l"(v));
}
__device__ __forceinline__ unsigned long long dup32(float x) {
    unsigned b = __float_as_uint(x);
    return ((unsigned long long)b << 32) | (unsigned long long)b;
}

// ---------------- threefry2x32 (JAX-exact, 20 rounds) ----------------
__device__ __forceinline__ uint32_t rotl32(uint32_t x, int r) {
    return (x << r) | (x >> (32 - r));
}

__device__ __forceinline__ void threefry2x32(uint32_t k0, uint32_t k1,
                                             uint32_t x0, uint32_t x1,
                                             uint32_t& o0, uint32_t& o1) {
    uint32_t ks0 = k0, ks1 = k1, ks2 = k0 ^ k1 ^ 0x1BD11BDAu;
    x0 += ks0; x1 += ks1;
    x0 += x1; x1 = rotl32(x1, 13); x1 ^= x0;
    x0 += x1; x1 = rotl32(x1, 15); x1 ^= x0;
    x0 += x1; x1 = rotl32(x1, 26); x1 ^= x0;
    x0 += x1; x1 = rotl32(x1,  6); x1 ^= x0;
    x0 += ks1; x1 += ks2 + 1u;
    x0 += x1; x1 = rotl32(x1, 17); x1 ^= x0;
    x0 += x1; x1 = rotl32(x1, 29); x1 ^= x0;
    x0 += x1; x1 = rotl32(x1, 16); x1 ^= x0;
    x0 += x1; x1 = rotl32(x1, 24); x1 ^= x0;
    x0 += ks2; x1 += ks0 + 2u;
    x0 += x1; x1 = rotl32(x1, 13); x1 ^= x0;
    x0 += x1; x1 = rotl32(x1, 15); x1 ^= x0;
    x0 += x1; x1 = rotl32(x1, 26); x1 ^= x0;
    x0 += x1; x1 = rotl32(x1,  6); x1 ^= x0;
    x0 += ks0; x1 += ks1 + 3u;
    x0 += x1; x1 = rotl32(x1, 17); x1 ^= x0;
    x0 += x1; x1 = rotl32(x1, 29); x1 ^= x0;
    x0 += x1; x1 = rotl32(x1, 16); x1 ^= x0;
    x0 += x1; x1 = rotl32(x1, 24); x1 ^= x0;
    x0 += ks1; x1 += ks2 + 4u;
    x0 += x1; x1 = rotl32(x1, 13); x1 ^= x0;
    x0 += x1; x1 = rotl32(x1, 15); x1 ^= x0;
    x0 += x1; x1 = rotl32(x1, 26); x1 ^= x0;
    x0 += x1; x1 = rotl32(x1,  6); x1 ^= x0;
    x0 += ks2; x1 += ks0 + 5u;
    o0 = x0; o1 = x1;
}

__device__ __forceinline__ float bits_to_uniform(uint32_t bits) {
    return __uint_as_float((bits >> 9) | 0x3f800000u) - 1.0f;
}

// ---------------- kernel A: prep (tv, tv2, barycenters, resets) -------------
__global__ void prep_kernel(const float* __restrict__ ov,
                            const int*   __restrict__ of,
                            const float* __restrict__ sv,
                            const int*   __restrict__ sf) {
    int i = blockIdx.x * 256 + threadIdx.x;
    if (i < N_OV) {
        float x = ov[3 * i], y = ov[3 * i + 1], z = ov[3 * i + 2];
        float nx = -2.0f * x, ny = -2.0f * y, nz = -2.0f * z;
        float w = x * x + y * y + z * z;
        g_tv[i] = make_float4(nx, ny, nz, w);
        g_tv2[2 * i]     = make_ulonglong2(dup32(nx), dup32(ny));
        g_tv2[2 * i + 1] = make_ulonglong2(dup32(nz), dup32(w));
    }
    if (i < N_OF) {
        int f0 = of[3 * i], f1 = of[3 * i + 1], f2 = of[3 * i + 2];
        float bx = (ov[3 * f0] + ov[3 * f1] + ov[3 * f2]) / 3.0f;
        float by = (ov[3 * f0 + 1] + ov[3 * f1 + 1] + ov[3 * f2 + 1]) / 3.0f;
        float bz = (ov[3 * f0 + 2] + ov[3 * f1 + 2] + ov[3 * f2 + 2]) / 3.0f;
        g_ob[i] = make_float4(-2.0f * bx, -2.0f * by, -2.0f * bz,
                              bx * bx + by * by + bz * bz);
    }
    if (i < N_SF) {
        int f0 = sf[3 * i], f1 = sf[3 * i + 1], f2 = sf[3 * i + 2];
        float bx = (sv[3 * f0] + sv[3 * f1] + sv[3 * f2]) / 3.0f;
        float by = (sv[3 * f0 + 1] + sv[3 * f1 + 1] + sv[3 * f2 + 1]) / 3.0f;
        float bz = (sv[3 * f0 + 2] + sv[3 * f1 + 2] + sv[3 * f2 + 2]) / 3.0f;
        g_sb[i] = make_float4(bx, by, bz, bx * bx + by * by + bz * bz);
        g_minfwd[i] = 0x7f800000u;  // +inf
    }
    if (i == 0) g_maxbits = 0u;
}

// ---------------- kernel B: forward min (brute force, chunked) ----------------
__global__ void __launch_bounds__(128) forward_kernel() {
    __shared__ float4 sob[FWD_CHUNK];
    int tid = threadIdx.x;
    int q = blockIdx.x * 128 + tid;
    int cbase = blockIdx.y * FWD_CHUNK;
    for (int k = tid; k < FWD_CHUNK; k += 128) sob[k] = g_ob[cbase + k];
    __syncthreads();
    if (q < N_SF) {
        float4 Q = g_sb[q];
        float m = 3.0e38f;
#pragma unroll 5
        for (int k = 0; k < FWD_CHUNK; k++) {
            float4 v = sob[k];
            float t = fmaf(v.x, Q.x, fmaf(v.y, Q.y, fmaf(v.z, Q.z, v.w)));
            m = fminf(m, t);
        }
        float d2 = fmaxf(m + Q.w, 0.0f);
        atomicMin(&g_minfwd[q], __float_as_uint(d2));
    }
}

// ---------------- kernel C: sample generation (partitionable threefry) ------
__device__ __forceinline__ float4 make_sample(int s, uint32_t bits_u1, uint32_t bits_r2,
                                              const float* __restrict__ sv,
                                              const int*   __restrict__ sf) {
    float u1 = bits_to_uniform(bits_u1);
    float r2 = bits_to_uniform(bits_r2);
    float sq = sqrtf(u1);
    float a = 1.0f - sq;
    float b = sq * (1.0f - r2);
    float c = sq * r2;
    int f = s / NSAMP;
    int i0 = sf[3 * f], i1 = sf[3 * f + 1], i2 = sf[3 * f + 2];
    float x = a * sv[3 * i0]     + b * sv[3 * i1]     + c * sv[3 * i2];
    float y = a * sv[3 * i0 + 1] + b * sv[3 * i1 + 1] + c * sv[3 * i2 + 1];
    float z = a * sv[3 * i0 + 2] + b * sv[3 * i1 + 2] + c * sv[3 * i2 + 2];
    return make_float4(x, y, z, x * x + y * y + z * z);
}

__global__ void gen_samples_kernel(const float* __restrict__ sv,
                                   const int*   __restrict__ sf) {
    int j = blockIdx.x * 256 + threadIdx.x;
    if (j >= N_SAMPLES_PAD) return;

    uint32_t rk1_0, rk1_1, rk2_0, rk2_1;
    threefry2x32(0u, 42u, 0u, 0u, rk1_0, rk1_1);  // rk1 = fold_in(key, 0)
    threefry2x32(0u, 42u, 0u, 1u, rk2_0, rk2_1);  // rk2 = fold_in(key, 1)

    int s = (j < N_SAMPLES) ? j : 0;   // padding clones sample 0

    uint32_t a0, a1, b0, b1;
    threefry2x32(rk1_0, rk1_1, 0u, (uint32_t)s, a0, a1);
    threefry2x32(rk2_0, rk2_1, 0u, (uint32_t)s, b0, b1);
    g_samples[j] = make_sample(s, a0 ^ a1, b0 ^ b1, sv, sf);
}

// ---------------- kernel D: reverse 1-NN (dominant, packed f32x2) ----------
__global__ void __launch_bounds__(128) reverse_kernel() {
    __shared__ ulonglong2 sv[2 * REV_TILE];   // 64 KB: [2k]=(vx2,vy2) [2k+1]=(vz2,vw2)
    int tid = threadIdx.x;
    int base = blockIdx.x * 1024;

    long long px2[4], py2[4], pz2[4];
    float m[8];
#pragma unroll
    for (int p = 0; p < 4; p++) {
        int s = base + p * 256 + 2 * tid;
        float4 sa = g_samples[s];
        float4 sb = g_samples[s + 1];
        px2[p] = pack2(sa.x, sb.x);
        py2[p] = pack2(sa.y, sb.y);
        pz2[p] = pack2(sa.z, sb.z);
        m[2 * p] = 3.0e38f;
        m[2 * p + 1] = 3.0e38f;
    }

    for (int t0 = 0; t0 < N_OV; t0 += REV_TILE) {
        __syncthreads();
        for (int k = tid; k < REV_TILE; k += 128) {
            sv[2 * k]     = g_tv2[2 * (t0 + k)];
            sv[2 * k + 1] = g_tv2[2 * (t0 + k) + 1];
        }
        __syncthreads();
#pragma unroll 4
        for (int k = 0; k < REV_TILE; k++) {
            ulonglong2 e0 = sv[2 * k];
            ulonglong2 e1 = sv[2 * k + 1];
            long long vx2 = (long long)e0.x;
            long long vy2 = (long long)e0.y;
            long long vz2 = (long long)e1.x;
            long long vw2 = (long long)e1.y;
#pragma unroll
            for (int p = 0; p < 4; p++) {
                long long t = fma2(vx2, px2[p], vw2);
                t = fma2(vy2, py2[p], t);
                t = fma2(vz2, pz2[p], t);
                float lo, hi;
                unpack2(t, lo, hi);
                m[2 * p]     = fminf(m[2 * p],     lo);
                m[2 * p + 1] = fminf(m[2 * p + 1], hi);
            }
        }
    }

    float lmax = 0.0f;
#pragma unroll
    for (int p = 0; p < 4; p++) {
        int s = base + p * 256 + 2 * tid;
        float pp0 = g_samples[s].w;
        float pp1 = g_samples[s + 1].w;
        float d0 = sqrtf(fmaxf(m[2 * p] + pp0, 0.0f));
        float d1 = sqrtf(fmaxf(m[2 * p + 1] + pp1, 0.0f));
        g_dist[s] = d0;
        g_dist[s + 1] = d1;
        lmax = fmaxf(lmax, fmaxf(d0, d1));
    }

    __shared__ float red[128];
    red[tid] = lmax;
    __syncthreads();
#pragma unroll
    for (int o = 64; o > 0; o >>= 1) {
        if (tid < o) red[tid] = fmaxf(red[tid], red[tid + o]);
        __syncthreads();
    }
    if (tid == 0) atomicMax(&g_maxbits, __float_as_uint(red[0]));
}

// ---------------- kernel E: deterministic final reduction ----------------
__global__ void __launch_bounds__(512) final_kernel(const float* __restrict__ fp,
                                                    float* __restrict__ out) {
    __shared__ double red[512];
    int tid = threadIdx.x;

    double fwd = 0.0, pen = 0.0, rev = 0.0;
    for (int i = tid; i < N_SF; i += 512) {
        float p = fp[i];
        float d2 = __uint_as_float(g_minfwd[i]);
        fwd += (double)(p * sqrtf(d2));
        pen += (double)(1.0f - p);
    }
    for (int s = tid; s < N_SAMPLES; s += 512) {
        rev += (double)(fp[s / NSAMP] * g_dist[s]);
    }

    double totF, totP, totR;
    red[tid] = fwd; __syncthreads();
    for (int o = 256; o > 0; o >>= 1) { if (tid < o) red[tid] += red[tid + o]; __syncthreads(); }
    totF = red[0]; __syncthreads();
    red[tid] = pen; __syncthreads();
    for (int o = 256; o > 0; o >>= 1) { if (tid < o) red[tid] += red[tid + o]; __syncthreads(); }
    totP = red[0]; __syncthreads();
    red[tid] = rev; __syncthreads();
    for (int o = 256; o > 0; o >>= 1) { if (tid < o) red[tid] += red[tid + o]; __syncthreads(); }
    totR = red[0];

    if (tid == 0) {
        double maxd = (double)__uint_as_float(g_maxbits);
        double result = totF + 1e-4 * totP + totR / (maxd + 1e-8) * 0.1;
        out[0] = (float)result;
    }
}

// ---------------- launch ----------------
extern "C" void kernel_launch(void* const* d_in, const int* in_sizes, int n_in,
                              void* d_out, int out_size) {
    const float* ov = (const float*)d_in[0];  // original_vertices [20000,3]
    const int*   of = (const int*)  d_in[1];  // original_faces    [30000,3]
    const float* sv = (const float*)d_in[2];  // simplified_vertices [4000,3]
    const int*   sf = (const int*)  d_in[3];  // simplified_faces  [5000,3]
    const float* fp = (const float*)d_in[4];  // face_probabilities [5000]
    float* out = (float*)d_out;

    prep_kernel<<<(N_OF + 255) / 256, 256>>>(ov, of, sv, sf);
    gen_samples_kernel<<<(N_SAMPLES_PAD + 255) / 256, 256>>>(sv, sf);
    {
        dim3 grid((N_SF + 127) / 128, N_OF / FWD_CHUNK);
        forward_kernel<<<grid, 128>>>();
    }
    reverse_kernel<<<REV_BLOCKS, 128>>>();
    final_kernel<<<1, 512>>>(fp, out);
}

// round 4
// speedup vs baseline: 1.3739x; 1.1972x over previous
#include <cuda_runtime.h>
#include <cuda_bf16.h>
#include <stdint.h>

// ---------------- problem constants (static shapes) ----------------
#define N_OV 20000      // original vertices
#define N_OF 30000      // original faces
#define N_SV 4000       // simplified vertices
#define N_SF 5000       // simplified faces
#define NSAMP 50
#define N_SAMPLES 250000        // N_SF * NSAMP
#define N_SAMPLES_PAD 250880    // 245 * 1024
#define SAMPLE_GROUPS 245       // sample groups of 1024
#define V_SPLIT 2               // vertex-dimension split for reverse
#define V_HALF 10000            // N_OV / V_SPLIT
#define FWD_CHUNK 3000          // 10 chunks of original barycenters
#define REV_TILE 2000           // smem tile (5 tiles per half)
#define N_PART 251              // partial-sum blocks (250880/1000 rounded up)
#define PART_CHUNK 1000

// ---------------- device scratch (static, no runtime alloc) ----------------
__device__ float4        g_tv[N_OV];
__device__ ulonglong2    g_tv2[2 * N_OV];   // dup-lane pairs: [2i]=(vx2,vy2) [2i+1]=(vz2,vw2)
__device__ float4        g_ob[N_OF];
__device__ float4        g_sb[N_SF];
__device__ unsigned      g_minfwd[N_SF];
__device__ float4        g_samples[N_SAMPLES_PAD]; // (x,y,z,|p|^2)
__device__ unsigned      g_mind2[N_SAMPLES_PAD];   // min d2 bits (atomicMin)
__device__ float         g_dist[N_SAMPLES_PAD];
__device__ unsigned      g_maxbits;
__device__ double        g_part[N_PART];

// ---------------- packed f32x2 helpers ----------------
__device__ __forceinline__ long long pack2(float a, float b) {
    long long r;
    asm("mov.b64 %0, {%1, %2};" : "=l"(r) : "f"(a), "f"(b));
    return r;
}
__device__ __forceinline__ long long fma2(long long a, long long b, long long c) {
    long long d;
    asm("fma.rn.f32x2 %0, %1, %2, %3;" : "=l"(d) : "l"(a), "l"(b), "l"(c));
    return d;
}
__device__ __forceinline__ void unpack2(long long v, float& lo, float& hi) {
    asm("mov.b64 {%0, %1}, %2;" : "=f"(lo), "=f"(hi) : "l"(v));
}
__device__ __forceinline__ unsigned long long dup32(float x) {
    unsigned b = __float_as_uint(x);
    return ((unsigned long long)b << 32) | (unsigned long long)b;
}

// ---------------- threefry2x32 (JAX-exact, 20 rounds) ----------------
__device__ __forceinline__ uint32_t rotl32(uint32_t x, int r) {
    return (x << r) | (x >> (32 - r));
}

__device__ __forceinline__ void threefry2x32(uint32_t k0, uint32_t k1,
                                             uint32_t x0, uint32_t x1,
                                             uint32_t& o0, uint32_t& o1) {
    uint32_t ks0 = k0, ks1 = k1, ks2 = k0 ^ k1 ^ 0x1BD11BDAu;
    x0 += ks0; x1 += ks1;
    x0 += x1; x1 = rotl32(x1, 13); x1 ^= x0;
    x0 += x1; x1 = rotl32(x1, 15); x1 ^= x0;
    x0 += x1; x1 = rotl32(x1, 26); x1 ^= x0;
    x0 += x1; x1 = rotl32(x1,  6); x1 ^= x0;
    x0 += ks1; x1 += ks2 + 1u;
    x0 += x1; x1 = rotl32(x1, 17); x1 ^= x0;
    x0 += x1; x1 = rotl32(x1, 29); x1 ^= x0;
    x0 += x1; x1 = rotl32(x1, 16); x1 ^= x0;
    x0 += x1; x1 = rotl32(x1, 24); x1 ^= x0;
    x0 += ks2; x1 += ks0 + 2u;
    x0 += x1; x1 = rotl32(x1, 13); x1 ^= x0;
    x0 += x1; x1 = rotl32(x1, 15); x1 ^= x0;
    x0 += x1; x1 = rotl32(x1, 26); x1 ^= x0;
    x0 += x1; x1 = rotl32(x1,  6); x1 ^= x0;
    x0 += ks0; x1 += ks1 + 3u;
    x0 += x1; x1 = rotl32(x1, 17); x1 ^= x0;
    x0 += x1; x1 = rotl32(x1, 29); x1 ^= x0;
    x0 += x1; x1 = rotl32(x1, 16); x1 ^= x0;
    x0 += x1; x1 = rotl32(x1, 24); x1 ^= x0;
    x0 += ks1; x1 += ks2 + 4u;
    x0 += x1; x1 = rotl32(x1, 13); x1 ^= x0;
    x0 += x1; x1 = rotl32(x1, 15); x1 ^= x0;
    x0 += x1; x1 = rotl32(x1, 26); x1 ^= x0;
    x0 += x1; x1 = rotl32(x1,  6); x1 ^= x0;
    x0 += ks2; x1 += ks0 + 5u;
    o0 = x0; o1 = x1;
}

__device__ __forceinline__ float bits_to_uniform(uint32_t bits) {
    return __uint_as_float((bits >> 9) | 0x3f800000u) - 1.0f;
}

// ---------------- kernel A: prep ----------------
__global__ void prep_kernel(const float* __restrict__ ov,
                            const int*   __restrict__ of,
                            const float* __restrict__ sv,
                            const int*   __restrict__ sf) {
    int i = blockIdx.x * 256 + threadIdx.x;
    if (i < N_OV) {
        float x = ov[3 * i], y = ov[3 * i + 1], z = ov[3 * i + 2];
        float nx = -2.0f * x, ny = -2.0f * y, nz = -2.0f * z;
        float w = x * x + y * y + z * z;
        g_tv[i] = make_float4(nx, ny, nz, w);
        g_tv2[2 * i]     = make_ulonglong2(dup32(nx), dup32(ny));
        g_tv2[2 * i + 1] = make_ulonglong2(dup32(nz), dup32(w));
    }
    if (i < N_OF) {
        int f0 = of[3 * i], f1 = of[3 * i + 1], f2 = of[3 * i + 2];
        float bx = (ov[3 * f0] + ov[3 * f1] + ov[3 * f2]) / 3.0f;
        float by = (ov[3 * f0 + 1] + ov[3 * f1 + 1] + ov[3 * f2 + 1]) / 3.0f;
        float bz = (ov[3 * f0 + 2] + ov[3 * f1 + 2] + ov[3 * f2 + 2]) / 3.0f;
        g_ob[i] = make_float4(-2.0f * bx, -2.0f * by, -2.0f * bz,
                              bx * bx + by * by + bz * bz);
    }
    if (i < N_SF) {
        int f0 = sf[3 * i], f1 = sf[3 * i + 1], f2 = sf[3 * i + 2];
        float bx = (sv[3 * f0] + sv[3 * f1] + sv[3 * f2]) / 3.0f;
        float by = (sv[3 * f0 + 1] + sv[3 * f1 + 1] + sv[3 * f2 + 1]) / 3.0f;
        float bz = (sv[3 * f0 + 2] + sv[3 * f1 + 2] + sv[3 * f2 + 2]) / 3.0f;
        g_sb[i] = make_float4(bx, by, bz, bx * bx + by * by + bz * bz);
        g_minfwd[i] = 0x7f800000u;
    }
    if (i == 0) g_maxbits = 0u;
}

// ---------------- kernel B: forward min ----------------
__global__ void __launch_bounds__(128) forward_kernel() {
    __shared__ float4 sob[FWD_CHUNK];
    int tid = threadIdx.x;
    int q = blockIdx.x * 128 + tid;
    int cbase = blockIdx.y * FWD_CHUNK;
    for (int k = tid; k < FWD_CHUNK; k += 128) sob[k] = g_ob[cbase + k];
    __syncthreads();
    if (q < N_SF) {
        float4 Q = g_sb[q];
        float m = 3.0e38f;
#pragma unroll 5
        for (int k = 0; k < FWD_CHUNK; k++) {
            float4 v = sob[k];
            float t = fmaf(v.x, Q.x, fmaf(v.y, Q.y, fmaf(v.z, Q.z, v.w)));
            m = fminf(m, t);
        }
        float d2 = fmaxf(m + Q.w, 0.0f);
        atomicMin(&g_minfwd[q], __float_as_uint(d2));
    }
}

// ---------------- kernel C: sample generation (partitionable threefry) ------
__device__ __forceinline__ float4 make_sample(int s, uint32_t bits_u1, uint32_t bits_r2,
                                              const float* __restrict__ sv,
                                              const int*   __restrict__ sf) {
    float u1 = bits_to_uniform(bits_u1);
    float r2 = bits_to_uniform(bits_r2);
    float sq = sqrtf(u1);
    float a = 1.0f - sq;
    float b = sq * (1.0f - r2);
    float c = sq * r2;
    int f = s / NSAMP;
    int i0 = sf[3 * f], i1 = sf[3 * f + 1], i2 = sf[3 * f + 2];
    float x = a * sv[3 * i0]     + b * sv[3 * i1]     + c * sv[3 * i2];
    float y = a * sv[3 * i0 + 1] + b * sv[3 * i1 + 1] + c * sv[3 * i2 + 1];
    float z = a * sv[3 * i0 + 2] + b * sv[3 * i1 + 2] + c * sv[3 * i2 + 2];
    return make_float4(x, y, z, x * x + y * y + z * z);
}

__global__ void gen_samples_kernel(const float* __restrict__ sv,
                                   const int*   __restrict__ sf) {
    int j = blockIdx.x * 256 + threadIdx.x;
    if (j >= N_SAMPLES_PAD) return;

    uint32_t rk1_0, rk1_1, rk2_0, rk2_1;
    threefry2x32(0u, 42u, 0u, 0u, rk1_0, rk1_1);  // rk1 = fold_in(key, 0)
    threefry2x32(0u, 42u, 0u, 1u, rk2_0, rk2_1);  // rk2 = fold_in(key, 1)

    int s = (j < N_SAMPLES) ? j : 0;   // padding clones sample 0

    uint32_t a0, a1, b0, b1;
    threefry2x32(rk1_0, rk1_1, 0u, (uint32_t)s, a0, a1);
    threefry2x32(rk2_0, rk2_1, 0u, (uint32_t)s, b0, b1);
    g_samples[j] = make_sample(s, a0 ^ a1, b0 ^ b1, sv, sf);
    g_mind2[j] = 0x7f800000u;   // +inf
}

// ---------------- kernel D: reverse 1-NN (dominant, packed f32x2) ----------
// grid = SAMPLE_GROUPS * V_SPLIT; block b handles sample group (b % 245)
// against vertex half (b / 245); per-sample minima merged via atomicMin.
__global__ void __launch_bounds__(128) reverse_kernel() {
    __shared__ ulonglong2 sv[2 * REV_TILE];   // 64 KB
    int tid = threadIdx.x;
    int grp = blockIdx.x % SAMPLE_GROUPS;
    int vh  = blockIdx.x / SAMPLE_GROUPS;
    int base = grp * 1024;
    int vbase = vh * V_HALF;

    long long px2[4], py2[4], pz2[4];
    float m[8];
#pragma unroll
    for (int p = 0; p < 4; p++) {
        int s = base + p * 256 + 2 * tid;
        float4 sa = g_samples[s];
        float4 sb = g_samples[s + 1];
        px2[p] = pack2(sa.x, sb.x);
        py2[p] = pack2(sa.y, sb.y);
        pz2[p] = pack2(sa.z, sb.z);
        m[2 * p] = 3.0e38f;
        m[2 * p + 1] = 3.0e38f;
    }

    for (int t0 = 0; t0 < V_HALF; t0 += REV_TILE) {
        __syncthreads();
        for (int k = tid; k < REV_TILE; k += 128) {
            sv[2 * k]     = g_tv2[2 * (vbase + t0 + k)];
            sv[2 * k + 1] = g_tv2[2 * (vbase + t0 + k) + 1];
        }
        __syncthreads();
#pragma unroll 4
        for (int k = 0; k < REV_TILE; k++) {
            ulonglong2 e0 = sv[2 * k];
            ulonglong2 e1 = sv[2 * k + 1];
            long long vx2 = (long long)e0.x;
            long long vy2 = (long long)e0.y;
            long long vz2 = (long long)e1.x;
            long long vw2 = (long long)e1.y;
#pragma unroll
            for (int p = 0; p < 4; p++) {
                long long t = fma2(vx2, px2[p], vw2);
                t = fma2(vy2, py2[p], t);
                t = fma2(vz2, pz2[p], t);
                float lo, hi;
                unpack2(t, lo, hi);
                m[2 * p]     = fminf(m[2 * p],     lo);
                m[2 * p + 1] = fminf(m[2 * p + 1], hi);
            }
        }
    }

#pragma unroll
    for (int p = 0; p < 4; p++) {
        int s = base + p * 256 + 2 * tid;
        float d20 = fmaxf(m[2 * p]     + g_samples[s].w,     0.0f);
        float d21 = fmaxf(m[2 * p + 1] + g_samples[s + 1].w, 0.0f);
        atomicMin(&g_mind2[s],     __float_as_uint(d20));
        atomicMin(&g_mind2[s + 1], __float_as_uint(d21));
    }
}

// ---------------- kernel D2: sqrt + global max ----------------
__global__ void __launch_bounds__(256) rev_finalize_kernel() {
    int j = blockIdx.x * 256 + threadIdx.x;
    float d = 0.0f;
    if (j < N_SAMPLES_PAD) {
        d = sqrtf(__uint_as_float(g_mind2[j]));
        g_dist[j] = d;
    }
    // block max
    __shared__ float red[256];
    red[threadIdx.x] = d;
    __syncthreads();
#pragma unroll
    for (int o = 128; o > 0; o >>= 1) {
        if (threadIdx.x < o) red[threadIdx.x] = fmaxf(red[threadIdx.x], red[threadIdx.x + o]);
        __syncthreads();
    }
    if (threadIdx.x == 0) atomicMax(&g_maxbits, __float_as_uint(red[0]));
}

// ---------------- kernel E1: partial sums (fixed partition, deterministic) --
__global__ void __launch_bounds__(256) partial_kernel(const float* __restrict__ fp) {
    int b = blockIdx.x;
    int tid = threadIdx.x;
    int s0 = b * PART_CHUNK;
    double acc = 0.0;
    for (int i = tid; i < PART_CHUNK; i += 256) {
        int s = s0 + i;
        if (s < N_SAMPLES) acc += (double)(fp[s / NSAMP] * g_dist[s]);
    }
    __shared__ double red[256];
    red[tid] = acc;
    __syncthreads();
#pragma unroll
    for (int o = 128; o > 0; o >>= 1) {
        if (tid < o) red[tid] += red[tid + o];
        __syncthreads();
    }
    if (tid == 0) g_part[b] = red[0];
}

// ---------------- kernel E2: final ----------------
__global__ void __launch_bounds__(512) final_kernel(const float* __restrict__ fp,
                                                    float* __restrict__ out) {
    __shared__ double red[512];
    int tid = threadIdx.x;

    double fwd = 0.0, pen = 0.0, rev = 0.0;
    for (int i = tid; i < N_SF; i += 512) {
        float p = fp[i];
        float d2 = __uint_as_float(g_minfwd[i]);
        fwd += (double)(p * sqrtf(d2));
        pen += (double)(1.0f - p);
    }
    for (int b = tid; b < N_PART; b += 512) rev += g_part[b];

    double totF, totP, totR;
    red[tid] = fwd; __syncthreads();
    for (int o = 256; o > 0; o >>= 1) { if (tid < o) red[tid] += red[tid + o]; __syncthreads(); }
    totF = red[0]; __syncthreads();
    red[tid] = pen; __syncthreads();
    for (int o = 256; o > 0; o >>= 1) { if (tid < o) red[tid] += red[tid + o]; __syncthreads(); }
    totP = red[0]; __syncthreads();
    red[tid] = rev; __syncthreads();
    for (int o = 256; o > 0; o >>= 1) { if (tid < o) red[tid] += red[tid + o]; __syncthreads(); }
    totR = red[0];

    if (tid == 0) {
        double maxd = (double)__uint_as_float(g_maxbits);
        double result = totF + 1e-4 * totP + totR / (maxd + 1e-8) * 0.1;
        out[0] = (float)result;
    }
}

// ---------------- launch ----------------
extern "C" void kernel_launch(void* const* d_in, const int* in_sizes, int n_in,
                              void* d_out, int out_size) {
    const float* ov = (const float*)d_in[0];
    const int*   of = (const int*)  d_in[1];
    const float* sv = (const float*)d_in[2];
    const int*   sf = (const int*)  d_in[3];
    const float* fp = (const float*)d_in[4];
    float* out = (float*)d_out;

    prep_kernel<<<(N_OF + 255) / 256, 256>>>(ov, of, sv, sf);
    gen_samples_kernel<<<(N_SAMPLES_PAD + 255) / 256, 256>>>(sv, sf);
    {
        dim3 grid((N_SF + 127) / 128, N_OF / FWD_CHUNK);
        forward_kernel<<<grid, 128>>>();
    }
    reverse_kernel<<<SAMPLE_GROUPS * V_SPLIT, 128>>>();
    rev_finalize_kernel<<<(N_SAMPLES_PAD + 255) / 256, 256>>>();
    partial_kernel<<<N_PART, 256>>>(fp);
    final_kernel<<<1, 512>>>(fp, out);
}

// round 5
// speedup vs baseline: 1.5218x; 1.1077x over previous
#include <cuda_runtime.h>
#include <cuda_bf16.h>
#include <stdint.h>

// ---------------- problem constants (static shapes) ----------------
#define N_OV 20000      // original vertices
#define N_OF 30000      // original faces
#define N_SV 4000       // simplified vertices
#define N_SF 5000       // simplified faces
#define NSAMP 50
#define N_SAMPLES 250000        // N_SF * NSAMP
#define N_SAMPLES_PAD 250880    // 245 * 1024
#define SAMPLE_GROUPS 245       // sample groups of 1024
#define V_SPLIT 4               // vertex-dimension split for reverse
#define V_PART 5000             // N_OV / V_SPLIT
#define FWD_CHUNK 3000          // 10 chunks of original barycenters
#define REV_TILE 1000           // smem tile (32 KB, 5 tiles per part)
#define N_PART 251              // partial-sum blocks
#define PART_CHUNK 1000

// ---------------- device scratch (static, no runtime alloc) ----------------
__device__ float4        g_tv[N_OV];
__device__ ulonglong2    g_tv2[2 * N_OV];   // dup-lane pairs: [2i]=(vx2,vy2) [2i+1]=(vz2,vw2)
__device__ float4        g_ob[N_OF];
__device__ float4        g_sb[N_SF];
__device__ unsigned      g_minfwd[N_SF];
__device__ float4        g_samples[N_SAMPLES_PAD]; // (x,y,z,|p|^2)
__device__ unsigned      g_mind2[N_SAMPLES_PAD];   // min d2 bits (atomicMin)
__device__ float         g_dist[N_SAMPLES_PAD];
__device__ unsigned      g_maxbits;
__device__ double        g_part[N_PART];

// ---------------- packed f32x2 helpers ----------------
__device__ __forceinline__ long long pack2(float a, float b) {
    long long r;
    asm("mov.b64 %0, {%1, %2};" : "=l"(r) : "f"(a), "f"(b));
    return r;
}
__device__ __forceinline__ long long fma2(long long a, long long b, long long c) {
    long long d;
    asm("fma.rn.f32x2 %0, %1, %2, %3;" : "=l"(d) : "l"(a), "l"(b), "l"(c));
    return d;
}
__device__ __forceinline__ void unpack2(long long v, float& lo, float& hi) {
    asm("mov.b64 {%0, %1}, %2;" : "=f"(lo), "=f"(hi) : "l"(v));
}
__device__ __forceinline__ unsigned long long dup32(float x) {
    unsigned b = __float_as_uint(x);
    return ((unsigned long long)b << 32) | (unsigned long long)b;
}

// ---------------- threefry2x32 (JAX-exact, 20 rounds) ----------------
__device__ __forceinline__ uint32_t rotl32(uint32_t x, int r) {
    return (x << r) | (x >> (32 - r));
}

__device__ __forceinline__ void threefry2x32(uint32_t k0, uint32_t k1,
                                             uint32_t x0, uint32_t x1,
                                             uint32_t& o0, uint32_t& o1) {
    uint32_t ks0 = k0, ks1 = k1, ks2 = k0 ^ k1 ^ 0x1BD11BDAu;
    x0 += ks0; x1 += ks1;
    x0 += x1; x1 = rotl32(x1, 13); x1 ^= x0;
    x0 += x1; x1 = rotl32(x1, 15); x1 ^= x0;
    x0 += x1; x1 = rotl32(x1, 26); x1 ^= x0;
    x0 += x1; x1 = rotl32(x1,  6); x1 ^= x0;
    x0 += ks1; x1 += ks2 + 1u;
    x0 += x1; x1 = rotl32(x1, 17); x1 ^= x0;
    x0 += x1; x1 = rotl32(x1, 29); x1 ^= x0;
    x0 += x1; x1 = rotl32(x1, 16); x1 ^= x0;
    x0 += x1; x1 = rotl32(x1, 24); x1 ^= x0;
    x0 += ks2; x1 += ks0 + 2u;
    x0 += x1; x1 = rotl32(x1, 13); x1 ^= x0;
    x0 += x1; x1 = rotl32(x1, 15); x1 ^= x0;
    x0 += x1; x1 = rotl32(x1, 26); x1 ^= x0;
    x0 += x1; x1 = rotl32(x1,  6); x1 ^= x0;
    x0 += ks0; x1 += ks1 + 3u;
    x0 += x1; x1 = rotl32(x1, 17); x1 ^= x0;
    x0 += x1; x1 = rotl32(x1, 29); x1 ^= x0;
    x0 += x1; x1 = rotl32(x1, 16); x1 ^= x0;
    x0 += x1; x1 = rotl32(x1, 24); x1 ^= x0;
    x0 += ks1; x1 += ks2 + 4u;
    x0 += x1; x1 = rotl32(x1, 13); x1 ^= x0;
    x0 += x1; x1 = rotl32(x1, 15); x1 ^= x0;
    x0 += x1; x1 = rotl32(x1, 26); x1 ^= x0;
    x0 += x1; x1 = rotl32(x1,  6); x1 ^= x0;
    x0 += ks2; x1 += ks0 + 5u;
    o0 = x0; o1 = x1;
}

__device__ __forceinline__ float bits_to_uniform(uint32_t bits) {
    return __uint_as_float((bits >> 9) | 0x3f800000u) - 1.0f;
}

// ---------------- kernel A: prep ----------------
__global__ void prep_kernel(const float* __restrict__ ov,
                            const int*   __restrict__ of,
                            const float* __restrict__ sv,
                            const int*   __restrict__ sf) {
    int i = blockIdx.x * 256 + threadIdx.x;
    if (i < N_OV) {
        float x = ov[3 * i], y = ov[3 * i + 1], z = ov[3 * i + 2];
        float nx = -2.0f * x, ny = -2.0f * y, nz = -2.0f * z;
        float w = x * x + y * y + z * z;
        g_tv[i] = make_float4(nx, ny, nz, w);
        g_tv2[2 * i]     = make_ulonglong2(dup32(nx), dup32(ny));
        g_tv2[2 * i + 1] = make_ulonglong2(dup32(nz), dup32(w));
    }
    if (i < N_OF) {
        int f0 = of[3 * i], f1 = of[3 * i + 1], f2 = of[3 * i + 2];
        float bx = (ov[3 * f0] + ov[3 * f1] + ov[3 * f2]) / 3.0f;
        float by = (ov[3 * f0 + 1] + ov[3 * f1 + 1] + ov[3 * f2 + 1]) / 3.0f;
        float bz = (ov[3 * f0 + 2] + ov[3 * f1 + 2] + ov[3 * f2 + 2]) / 3.0f;
        g_ob[i] = make_float4(-2.0f * bx, -2.0f * by, -2.0f * bz,
                              bx * bx + by * by + bz * bz);
    }
    if (i < N_SF) {
        int f0 = sf[3 * i], f1 = sf[3 * i + 1], f2 = sf[3 * i + 2];
        float bx = (sv[3 * f0] + sv[3 * f1] + sv[3 * f2]) / 3.0f;
        float by = (sv[3 * f0 + 1] + sv[3 * f1 + 1] + sv[3 * f2 + 1]) / 3.0f;
        float bz = (sv[3 * f0 + 2] + sv[3 * f1 + 2] + sv[3 * f2 + 2]) / 3.0f;
        g_sb[i] = make_float4(bx, by, bz, bx * bx + by * by + bz * bz);
        g_minfwd[i] = 0x7f800000u;
    }
    if (i == 0) g_maxbits = 0u;
}

// ---------------- kernel B: forward min ----------------
__global__ void __launch_bounds__(128) forward_kernel() {
    __shared__ float4 sob[FWD_CHUNK];
    int tid = threadIdx.x;
    int q = blockIdx.x * 128 + tid;
    int cbase = blockIdx.y * FWD_CHUNK;
    for (int k = tid; k < FWD_CHUNK; k += 128) sob[k] = g_ob[cbase + k];
    __syncthreads();
    if (q < N_SF) {
        float4 Q = g_sb[q];
        float m = 3.0e38f;
#pragma unroll 5
        for (int k = 0; k < FWD_CHUNK; k++) {
            float4 v = sob[k];
            float t = fmaf(v.x, Q.x, fmaf(v.y, Q.y, fmaf(v.z, Q.z, v.w)));
            m = fminf(m, t);
        }
        float d2 = fmaxf(m + Q.w, 0.0f);
        atomicMin(&g_minfwd[q], __float_as_uint(d2));
    }
}

// ---------------- kernel C: sample generation (partitionable threefry) ------
__device__ __forceinline__ float4 make_sample(int s, uint32_t bits_u1, uint32_t bits_r2,
                                              const float* __restrict__ sv,
                                              const int*   __restrict__ sf) {
    float u1 = bits_to_uniform(bits_u1);
    float r2 = bits_to_uniform(bits_r2);
    float sq = sqrtf(u1);
    float a = 1.0f - sq;
    float b = sq * (1.0f - r2);
    float c = sq * r2;
    int f = s / NSAMP;
    int i0 = sf[3 * f], i1 = sf[3 * f + 1], i2 = sf[3 * f + 2];
    float x = a * sv[3 * i0]     + b * sv[3 * i1]     + c * sv[3 * i2];
    float y = a * sv[3 * i0 + 1] + b * sv[3 * i1 + 1] + c * sv[3 * i2 + 1];
    float z = a * sv[3 * i0 + 2] + b * sv[3 * i1 + 2] + c * sv[3 * i2 + 2];
    return make_float4(x, y, z, x * x + y * y + z * z);
}

__global__ void gen_samples_kernel(const float* __restrict__ sv,
                                   const int*   __restrict__ sf) {
    int j = blockIdx.x * 256 + threadIdx.x;
    if (j >= N_SAMPLES_PAD) return;

    uint32_t rk1_0, rk1_1, rk2_0, rk2_1;
    threefry2x32(0u, 42u, 0u, 0u, rk1_0, rk1_1);  // rk1 = fold_in(key, 0)
    threefry2x32(0u, 42u, 0u, 1u, rk2_0, rk2_1);  // rk2 = fold_in(key, 1)

    int s = (j < N_SAMPLES) ? j : 0;   // padding clones sample 0

    uint32_t a0, a1, b0, b1;
    threefry2x32(rk1_0, rk1_1, 0u, (uint32_t)s, a0, a1);
    threefry2x32(rk2_0, rk2_1, 0u, (uint32_t)s, b0, b1);
    g_samples[j] = make_sample(s, a0 ^ a1, b0 ^ b1, sv, sf);
    g_mind2[j] = 0x7f800000u;   // +inf
}

// ---------------- kernel D: reverse 1-NN (dominant, packed f32x2) ----------
// grid = SAMPLE_GROUPS * V_SPLIT; block b: sample group (b % 245),
// vertex quarter (b / 245); minima merged via atomicMin on d2 bits.
__global__ void __launch_bounds__(128, 6) reverse_kernel() {
    __shared__ ulonglong2 sv[2 * REV_TILE];   // 32 KB
    int tid = threadIdx.x;
    int grp = blockIdx.x % SAMPLE_GROUPS;
    int vh  = blockIdx.x / SAMPLE_GROUPS;
    int base = grp * 1024;
    int vbase = vh * V_PART;

    long long px2[4], py2[4], pz2[4];
    float m[8];
#pragma unroll
    for (int p = 0; p < 4; p++) {
        int s = base + p * 256 + 2 * tid;
        float4 sa = g_samples[s];
        float4 sb = g_samples[s + 1];
        px2[p] = pack2(sa.x, sb.x);
        py2[p] = pack2(sa.y, sb.y);
        pz2[p] = pack2(sa.z, sb.z);
        m[2 * p] = 3.0e38f;
        m[2 * p + 1] = 3.0e38f;
    }

    for (int t0 = 0; t0 < V_PART; t0 += REV_TILE) {
        __syncthreads();
        for (int k = tid; k < REV_TILE; k += 128) {
            sv[2 * k]     = g_tv2[2 * (vbase + t0 + k)];
            sv[2 * k + 1] = g_tv2[2 * (vbase + t0 + k) + 1];
        }
        __syncthreads();
#pragma unroll 4
        for (int k = 0; k < REV_TILE; k++) {
            ulonglong2 e0 = sv[2 * k];
            ulonglong2 e1 = sv[2 * k + 1];
            long long vx2 = (long long)e0.x;
            long long vy2 = (long long)e0.y;
            long long vz2 = (long long)e1.x;
            long long vw2 = (long long)e1.y;
#pragma unroll
            for (int p = 0; p < 4; p++) {
                long long t = fma2(vx2, px2[p], vw2);
                t = fma2(vy2, py2[p], t);
                t = fma2(vz2, pz2[p], t);
                float lo, hi;
                unpack2(t, lo, hi);
                m[2 * p]     = fminf(m[2 * p],     lo);
                m[2 * p + 1] = fminf(m[2 * p + 1], hi);
            }
        }
    }

#pragma unroll
    for (int p = 0; p < 4; p++) {
        int s = base + p * 256 + 2 * tid;
        float d20 = fmaxf(m[2 * p]     + g_samples[s].w,     0.0f);
        float d21 = fmaxf(m[2 * p + 1] + g_samples[s + 1].w, 0.0f);
        atomicMin(&g_mind2[s],     __float_as_uint(d20));
        atomicMin(&g_mind2[s + 1], __float_as_uint(d21));
    }
}

// ---------------- kernel D2: sqrt + global max ----------------
__global__ void __launch_bounds__(256) rev_finalize_kernel() {
    int j = blockIdx.x * 256 + threadIdx.x;
    float d = 0.0f;
    if (j < N_SAMPLES_PAD) {
        d = sqrtf(__uint_as_float(g_mind2[j]));
        g_dist[j] = d;
    }
    __shared__ float red[256];
    red[threadIdx.x] = d;
    __syncthreads();
#pragma unroll
    for (int o = 128; o > 0; o >>= 1) {
        if (threadIdx.x < o) red[threadIdx.x] = fmaxf(red[threadIdx.x], red[threadIdx.x + o]);
        __syncthreads();
    }
    if (threadIdx.x == 0) atomicMax(&g_maxbits, __float_as_uint(red[0]));
}

// ---------------- kernel E1: partial sums (fixed partition, deterministic) --
__global__ void __launch_bounds__(256) partial_kernel(const float* __restrict__ fp) {
    int b = blockIdx.x;
    int tid = threadIdx.x;
    int s0 = b * PART_CHUNK;
    double acc = 0.0;
    for (int i = tid; i < PART_CHUNK; i += 256) {
        int s = s0 + i;
        if (s < N_SAMPLES) acc += (double)(fp[s / NSAMP] * g_dist[s]);
    }
    __shared__ double red[256];
    red[tid] = acc;
    __syncthreads();
#pragma unroll
    for (int o = 128; o > 0; o >>= 1) {
        if (tid < o) red[tid] += red[tid + o];
        __syncthreads();
    }
    if (tid == 0) g_part[b] = red[0];
}

// ---------------- kernel E2: final ----------------
__global__ void __launch_bounds__(512) final_kernel(const float* __restrict__ fp,
                                                    float* __restrict__ out) {
    __shared__ double red[512];
    int tid = threadIdx.x;

    double fwd = 0.0, pen = 0.0, rev = 0.0;
    for (int i = tid; i < N_SF; i += 512) {
        float p = fp[i];
        float d2 = __uint_as_float(g_minfwd[i]);
        fwd += (double)(p * sqrtf(d2));
        pen += (double)(1.0f - p);
    }
    for (int b = tid; b < N_PART; b += 512) rev += g_part[b];

    double totF, totP, totR;
    red[tid] = fwd; __syncthreads();
    for (int o = 256; o > 0; o >>= 1) { if (tid < o) red[tid] += red[tid + o]; __syncthreads(); }
    totF = red[0]; __syncthreads();
    red[tid] = pen; __syncthreads();
    for (int o = 256; o > 0; o >>= 1) { if (tid < o) red[tid] += red[tid + o]; __syncthreads(); }
    totP = red[0]; __syncthreads();
    red[tid] = rev; __syncthreads();
    for (int o = 256; o > 0; o >>= 1) { if (tid < o) red[tid] += red[tid + o]; __syncthreads(); }
    totR = red[0];

    if (tid == 0) {
        double maxd = (double)__uint_as_float(g_maxbits);
        double result = totF + 1e-4 * totP + totR / (maxd + 1e-8) * 0.1;
        out[0] = (float)result;
    }
}

// ---------------- launch ----------------
extern "C" void kernel_launch(void* const* d_in, const int* in_sizes, int n_in,
                              void* d_out, int out_size) {
    const float* ov = (const float*)d_in[0];
    const int*   of = (const int*)  d_in[1];
    const float* sv = (const float*)d_in[2];
    const int*   sf = (const int*)  d_in[3];
    const float* fp = (const float*)d_in[4];
    float* out = (float*)d_out;

    prep_kernel<<<(N_OF + 255) / 256, 256>>>(ov, of, sv, sf);
    gen_samples_kernel<<<(N_SAMPLES_PAD + 255) / 256, 256>>>(sv, sf);
    {
        dim3 grid((N_SF + 127) / 128, N_OF / FWD_CHUNK);
        forward_kernel<<<grid, 128>>>();
    }
    reverse_kernel<<<SAMPLE_GROUPS * V_SPLIT, 128>>>();
    rev_finalize_kernel<<<(N_SAMPLES_PAD + 255) / 256, 256>>>();
    partial_kernel<<<N_PART, 256>>>(fp);
    final_kernel<<<1, 512>>>(fp, out);
}

// round 6
// speedup vs baseline: 5.8352x; 3.8344x over previous
#include <cuda_runtime.h>
#include <cuda_bf16.h>
#include <stdint.h>

// ---------------- problem constants (static shapes) ----------------
#define N_OV 20000
#define N_OF 30000
#define N_SV 4000
#define N_SF 5000
#define NSAMP 50
#define N_SAMPLES 250000
#define FWD_CHUNK 3000
#define GRID_G 64
#define NCELLS (GRID_G * GRID_G * GRID_G)   // 262144
#define SCAN_BLOCKS 256                      // 256 * 1024 = NCELLS
#define REV_BLOCKS 977                       // ceil(250000/256)

// ---------------- device scratch (static, no runtime alloc) ----------------
__device__ float4    g_ob[N_OF];             // (-2bx,-2by,-2bz,|b|^2)
__device__ float4    g_sb[N_SF];             // (bx,by,bz,|b|^2)
__device__ unsigned  g_minfwd[N_SF];
__device__ float4    g_samples[N_SAMPLES];   // (x,y,z,|p|^2)
__device__ unsigned  g_maxbits;
__device__ double    g_part[REV_BLOCKS];
// grid structures
__device__ unsigned  g_bbox[6];              // ordered-float min xyz, max xyz
__device__ int       g_count[NCELLS];
__device__ int       g_cursor[NCELLS];
__device__ int       g_cellstart[NCELLS + 1];
__device__ int       g_blocksum[SCAN_BLOCKS];
__device__ int       g_blockoff[SCAN_BLOCKS];
__device__ float4    g_sorted[N_OV];         // (x,y,z,|v|^2) sorted by cell

// ---------------- ordered-float helpers ----------------
__device__ __forceinline__ unsigned f2o(float f) {
    unsigned u = __float_as_uint(f);
    return (u & 0x80000000u) ? ~u : (u | 0x80000000u);
}
__device__ __forceinline__ float o2f(unsigned u) {
    u = (u & 0x80000000u) ? (u & 0x7fffffffu) : ~u;
    return __uint_as_float(u);
}

// ---------------- threefry2x32 (JAX partitionable, 20 rounds) ----------------
__device__ __forceinline__ uint32_t rotl32(uint32_t x, int r) {
    return (x << r) | (x >> (32 - r));
}
__device__ __forceinline__ void threefry2x32(uint32_t k0, uint32_t k1,
                                             uint32_t x0, uint32_t x1,
                                             uint32_t& o0, uint32_t& o1) {
    uint32_t ks0 = k0, ks1 = k1, ks2 = k0 ^ k1 ^ 0x1BD11BDAu;
    x0 += ks0; x1 += ks1;
    x0 += x1; x1 = rotl32(x1, 13); x1 ^= x0;
    x0 += x1; x1 = rotl32(x1, 15); x1 ^= x0;
    x0 += x1; x1 = rotl32(x1, 26); x1 ^= x0;
    x0 += x1; x1 = rotl32(x1,  6); x1 ^= x0;
    x0 += ks1; x1 += ks2 + 1u;
    x0 += x1; x1 = rotl32(x1, 17); x1 ^= x0;
    x0 += x1; x1 = rotl32(x1, 29); x1 ^= x0;
    x0 += x1; x1 = rotl32(x1, 16); x1 ^= x0;
    x0 += x1; x1 = rotl32(x1, 24); x1 ^= x0;
    x0 += ks2; x1 += ks0 + 2u;
    x0 += x1; x1 = rotl32(x1, 13); x1 ^= x0;
    x0 += x1; x1 = rotl32(x1, 15); x1 ^= x0;
    x0 += x1; x1 = rotl32(x1, 26); x1 ^= x0;
    x0 += x1; x1 = rotl32(x1,  6); x1 ^= x0;
    x0 += ks0; x1 += ks1 + 3u;
    x0 += x1; x1 = rotl32(x1, 17); x1 ^= x0;
    x0 += x1; x1 = rotl32(x1, 29); x1 ^= x0;
    x0 += x1; x1 = rotl32(x1, 16); x1 ^= x0;
    x0 += x1; x1 = rotl32(x1, 24); x1 ^= x0;
    x0 += ks1; x1 += ks2 + 4u;
    x0 += x1; x1 = rotl32(x1, 13); x1 ^= x0;
    x0 += x1; x1 = rotl32(x1, 15); x1 ^= x0;
    x0 += x1; x1 = rotl32(x1, 26); x1 ^= x0;
    x0 += x1; x1 = rotl32(x1,  6); x1 ^= x0;
    x0 += ks2; x1 += ks0 + 5u;
    o0 = x0; o1 = x1;
}
__device__ __forceinline__ float bits_to_uniform(uint32_t bits) {
    return __uint_as_float((bits >> 9) | 0x3f800000u) - 1.0f;
}

// ---------------- kernel 0: init ----------------
__global__ void init_kernel() {
    int i = blockIdx.x * 256 + threadIdx.x;
    if (i < NCELLS) { g_count[i] = 0; g_cursor[i] = 0; }
    if (i == 0) {
        g_maxbits = 0u;
        g_bbox[0] = g_bbox[1] = g_bbox[2] = 0xFFFFFFFFu;  // min slots
        g_bbox[3] = g_bbox[4] = g_bbox[5] = 0u;           // max slots
    }
}

// ---------------- kernel A: prep (bbox, barycenters, resets) ----------------
__global__ void prep_kernel(const float* __restrict__ ov,
                            const int*   __restrict__ of,
                            const float* __restrict__ sv,
                            const int*   __restrict__ sf) {
    int i = blockIdx.x * 256 + threadIdx.x;

    // bbox of original vertices (warp-reduced, then lane-0 atomics)
    {
        float x, y, z;
        if (i < N_OV) { x = ov[3 * i]; y = ov[3 * i + 1]; z = ov[3 * i + 2]; }
        else          { x = y = z = 0.0f; }   // harmless filler inside data range? NO - use neutral
        float mnx = (i < N_OV) ? x :  3.0e38f, mxx = (i < N_OV) ? x : -3.0e38f;
        float mny = (i < N_OV) ? y :  3.0e38f, mxy = (i < N_OV) ? y : -3.0e38f;
        float mnz = (i < N_OV) ? z :  3.0e38f, mxz = (i < N_OV) ? z : -3.0e38f;
#pragma unroll
        for (int o = 16; o > 0; o >>= 1) {
            mnx = fminf(mnx, __shfl_xor_sync(0xffffffffu, mnx, o));
            mny = fminf(mny, __shfl_xor_sync(0xffffffffu, mny, o));
            mnz = fminf(mnz, __shfl_xor_sync(0xffffffffu, mnz, o));
            mxx = fmaxf(mxx, __shfl_xor_sync(0xffffffffu, mxx, o));
            mxy = fmaxf(mxy, __shfl_xor_sync(0xffffffffu, mxy, o));
            mxz = fmaxf(mxz, __shfl_xor_sync(0xffffffffu, mxz, o));
        }
        if ((threadIdx.x & 31) == 0 && (blockIdx.x * 256 + (threadIdx.x & ~31)) < N_OV) {
            atomicMin(&g_bbox[0], f2o(mnx));
            atomicMin(&g_bbox[1], f2o(mny));
            atomicMin(&g_bbox[2], f2o(mnz));
            atomicMax(&g_bbox[3], f2o(mxx));
            atomicMax(&g_bbox[4], f2o(mxy));
            atomicMax(&g_bbox[5], f2o(mxz));
        }
    }
    if (i < N_OF) {
        int f0 = of[3 * i], f1 = of[3 * i + 1], f2 = of[3 * i + 2];
        float bx = (ov[3 * f0] + ov[3 * f1] + ov[3 * f2]) / 3.0f;
        float by = (ov[3 * f0 + 1] + ov[3 * f1 + 1] + ov[3 * f2 + 1]) / 3.0f;
        float bz = (ov[3 * f0 + 2] + ov[3 * f1 + 2] + ov[3 * f2 + 2]) / 3.0f;
        g_ob[i] = make_float4(-2.0f * bx, -2.0f * by, -2.0f * bz,
                              bx * bx + by * by + bz * bz);
    }
    if (i < N_SF) {
        int f0 = sf[3 * i], f1 = sf[3 * i + 1], f2 = sf[3 * i + 2];
        float bx = (sv[3 * f0] + sv[3 * f1] + sv[3 * f2]) / 3.0f;
        float by = (sv[3 * f0 + 1] + sv[3 * f1 + 1] + sv[3 * f2 + 1]) / 3.0f;
        float bz = (sv[3 * f0 + 2] + sv[3 * f1 + 2] + sv[3 * f2 + 2]) / 3.0f;
        g_sb[i] = make_float4(bx, by, bz, bx * bx + by * by + bz * bz);
        g_minfwd[i] = 0x7f800000u;
    }
}

// ---------------- grid geometry helper ----------------
struct GridGeom { float x0, y0, z0, invh, h; };
__device__ __forceinline__ GridGeom load_geom() {
    GridGeom g;
    g.x0 = o2f(g_bbox[0]); g.y0 = o2f(g_bbox[1]); g.z0 = o2f(g_bbox[2]);
    float ex = o2f(g_bbox[3]) - g.x0;
    float ey = o2f(g_bbox[4]) - g.y0;
    float ez = o2f(g_bbox[5]) - g.z0;
    float e = fmaxf(fmaxf(ex, ey), fmaxf(ez, 1e-20f));
    g.h = e / (float)GRID_G;
    g.invh = (float)GRID_G / e;
    return g;
}
__device__ __forceinline__ int cell_coord(float v, float v0, float invh) {
    int c = (int)((v - v0) * invh);
    return min(max(c, 0), GRID_G - 1);
}

// ---------------- kernel B: forward min (brute force, chunked) ----------------
__global__ void __launch_bounds__(128) forward_kernel() {
    __shared__ float4 sob[FWD_CHUNK];
    int tid = threadIdx.x;
    int q = blockIdx.x * 128 + tid;
    int cbase = blockIdx.y * FWD_CHUNK;
    for (int k = tid; k < FWD_CHUNK; k += 128) sob[k] = g_ob[cbase + k];
    __syncthreads();
    if (q < N_SF) {
        float4 Q = g_sb[q];
        float m = 3.0e38f;
#pragma unroll 5
        for (int k = 0; k < FWD_CHUNK; k++) {
            float4 v = sob[k];
            float t = fmaf(v.x, Q.x, fmaf(v.y, Q.y, fmaf(v.z, Q.z, v.w)));
            m = fminf(m, t);
        }
        float d2 = fmaxf(m + Q.w, 0.0f);
        atomicMin(&g_minfwd[q], __float_as_uint(d2));
    }
}

// ---------------- kernel C: sample generation ----------------
__global__ void gen_samples_kernel(const float* __restrict__ sv,
                                   const int*   __restrict__ sf) {
    int j = blockIdx.x * 256 + threadIdx.x;
    if (j >= N_SAMPLES) return;

    uint32_t rk1_0, rk1_1, rk2_0, rk2_1;
    threefry2x32(0u, 42u, 0u, 0u, rk1_0, rk1_1);
    threefry2x32(0u, 42u, 0u, 1u, rk2_0, rk2_1);

    uint32_t a0, a1, b0, b1;
    threefry2x32(rk1_0, rk1_1, 0u, (uint32_t)j, a0, a1);
    threefry2x32(rk2_0, rk2_1, 0u, (uint32_t)j, b0, b1);

    float u1 = bits_to_uniform(a0 ^ a1);
    float r2 = bits_to_uniform(b0 ^ b1);
    float sq = sqrtf(u1);
    float a = 1.0f - sq;
    float b = sq * (1.0f - r2);
    float c = sq * r2;
    int f = j / NSAMP;
    int i0 = sf[3 * f], i1 = sf[3 * f + 1], i2 = sf[3 * f + 2];
    float x = a * sv[3 * i0]     + b * sv[3 * i1]     + c * sv[3 * i2];
    float y = a * sv[3 * i0 + 1] + b * sv[3 * i1 + 1] + c * sv[3 * i2 + 1];
    float z = a * sv[3 * i0 + 2] + b * sv[3 * i1 + 2] + c * sv[3 * i2 + 2];
    g_samples[j] = make_float4(x, y, z, x * x + y * y + z * z);
}

// ---------------- kernel D1: count vertices per cell ----------------
__global__ void count_kernel(const float* __restrict__ ov) {
    int i = blockIdx.x * 256 + threadIdx.x;
    if (i >= N_OV) return;
    GridGeom g = load_geom();
    int cx = cell_coord(ov[3 * i],     g.x0, g.invh);
    int cy = cell_coord(ov[3 * i + 1], g.y0, g.invh);
    int cz = cell_coord(ov[3 * i + 2], g.z0, g.invh);
    atomicAdd(&g_count[(cz * GRID_G + cy) * GRID_G + cx], 1);
}

// ---------------- kernel D2: block-level exclusive scan ----------------
__global__ void __launch_bounds__(1024) scan1_kernel() {
    __shared__ int sd[1024];
    int tid = threadIdx.x;
    int cell = blockIdx.x * 1024 + tid;
    int cnt = g_count[cell];
    sd[tid] = cnt;
    __syncthreads();
#pragma unroll
    for (int off = 1; off < 1024; off <<= 1) {
        int v = (tid >= off) ? sd[tid - off] : 0;
        __syncthreads();
        sd[tid] += v;
        __syncthreads();
    }
    g_cellstart[cell] = sd[tid] - cnt;   // exclusive within block
    if (tid == 1023) g_blocksum[blockIdx.x] = sd[1023];
}

// ---------------- kernel D3: scan of block sums ----------------
__global__ void __launch_bounds__(256) scan2_kernel() {
    __shared__ int sd[SCAN_BLOCKS];
    int tid = threadIdx.x;
    int v = g_blocksum[tid];
    sd[tid] = v;
    __syncthreads();
#pragma unroll
    for (int off = 1; off < SCAN_BLOCKS; off <<= 1) {
        int w = (tid >= off) ? sd[tid - off] : 0;
        __syncthreads();
        sd[tid] += w;
        __syncthreads();
    }
    g_blockoff[tid] = sd[tid] - v;
    if (tid == SCAN_BLOCKS - 1) g_cellstart[NCELLS] = sd[tid];
}

// ---------------- kernel D4: add block offsets ----------------
__global__ void scan3_kernel() {
    int cell = blockIdx.x * 256 + threadIdx.x;
    if (cell < NCELLS) g_cellstart[cell] += g_blockoff[cell >> 10];
}

// ---------------- kernel D5: scatter vertices into sorted order ------------
__global__ void scatter_kernel(const float* __restrict__ ov) {
    int i = blockIdx.x * 256 + threadIdx.x;
    if (i >= N_OV) return;
    GridGeom g = load_geom();
    float x = ov[3 * i], y = ov[3 * i + 1], z = ov[3 * i + 2];
    int cx = cell_coord(x, g.x0, g.invh);
    int cy = cell_coord(y, g.y0, g.invh);
    int cz = cell_coord(z, g.z0, g.invh);
    int c = (cz * GRID_G + cy) * GRID_G + cx;
    int pos = g_cellstart[c] + atomicAdd(&g_cursor[c], 1);
    g_sorted[pos] = make_float4(x, y, z, x * x + y * y + z * z);
}

// ---------------- kernel E: grid-accelerated exact 1-NN ----------------
__global__ void __launch_bounds__(256) reverse_grid_kernel(const float* __restrict__ fp) {
    int j = blockIdx.x * 256 + threadIdx.x;
    GridGeom g = load_geom();

    float d = 0.0f;
    double contrib = 0.0;
    if (j < N_SAMPLES) {
        float4 s = g_samples[j];
        float m2x = -2.0f * s.x, m2y = -2.0f * s.y, m2z = -2.0f * s.z;
        int cx = cell_coord(s.x, g.x0, g.invh);
        int cy = cell_coord(s.y, g.y0, g.invh);
        int cz = cell_coord(s.z, g.z0, g.invh);

        float best = 3.0e38f;   // best (t) where d2 = t + |s|^2
        for (int R = 0; R <= GRID_G; R++) {
            if (R > 0) {
                float lb = (float)(R - 1) * g.h;
                if (best + s.w <= lb * lb) break;
            }
            int zlo = max(cz - R, 0), zhi = min(cz + R, GRID_G - 1);
            int ylo = max(cy - R, 0), yhi = min(cy + R, GRID_G - 1);
            int xlo = max(cx - R, 0), xhi = min(cx + R, GRID_G - 1);
            for (int z = zlo; z <= zhi; z++) {
                bool ze = (z == cz - R) || (z == cz + R);
                for (int y = ylo; y <= yhi; y++) {
                    bool edge = ze || (y == cy - R) || (y == cy + R);
                    int rowbase = (z * GRID_G + y) * GRID_G;
                    if (edge) {
                        // full x span of this row is shell
                        int p0 = g_cellstart[rowbase + xlo];
                        int p1 = g_cellstart[rowbase + xhi + 1];
                        for (int p = p0; p < p1; p++) {
                            float4 v = g_sorted[p];
                            float t = fmaf(v.x, m2x, fmaf(v.y, m2y, fmaf(v.z, m2z, v.w)));
                            best = fminf(best, t);
                        }
                    } else {
                        // only x = cx-R and cx+R faces
                        int xa = cx - R, xb = cx + R;
                        if (xa >= 0) {
                            int c0 = rowbase + xa;
                            int p0 = g_cellstart[c0], p1 = g_cellstart[c0 + 1];
                            for (int p = p0; p < p1; p++) {
                                float4 v = g_sorted[p];
                                float t = fmaf(v.x, m2x, fmaf(v.y, m2y, fmaf(v.z, m2z, v.w)));
                                best = fminf(best, t);
                            }
                        }
                        if (xb <= GRID_G - 1) {
                            int c0 = rowbase + xb;
                            int p0 = g_cellstart[c0], p1 = g_cellstart[c0 + 1];
                            for (int p = p0; p < p1; p++) {
                                float4 v = g_sorted[p];
                                float t = fmaf(v.x, m2x, fmaf(v.y, m2y, fmaf(v.z, m2z, v.w)));
                                best = fminf(best, t);
                            }
                        }
                    }
                }
            }
            // whole grid covered?
            if (zlo == 0 && ylo == 0 && xlo == 0 &&
                zhi == GRID_G - 1 && yhi == GRID_G - 1 && xhi == GRID_G - 1) break;
        }
        d = sqrtf(fmaxf(best + s.w, 0.0f));
        contrib = (double)(fp[j / NSAMP] * d);
    }

    // block reductions: sum (double) and max (float)
    __shared__ double rsum[256];
    __shared__ float rmax[256];
    int tid = threadIdx.x;
    rsum[tid] = contrib;
    rmax[tid] = d;
    __syncthreads();
#pragma unroll
    for (int o = 128; o > 0; o >>= 1) {
        if (tid < o) {
            rsum[tid] += rsum[tid + o];
            rmax[tid] = fmaxf(rmax[tid], rmax[tid + o]);
        }
        __syncthreads();
    }
    if (tid == 0) {
        g_part[blockIdx.x] = rsum[0];
        atomicMax(&g_maxbits, __float_as_uint(rmax[0]));
    }
}

// ---------------- kernel F: final ----------------
__global__ void __launch_bounds__(512) final_kernel(const float* __restrict__ fp,
                                                    float* __restrict__ out) {
    __shared__ double red[512];
    int tid = threadIdx.x;

    double fwd = 0.0, pen = 0.0, rev = 0.0;
    for (int i = tid; i < N_SF; i += 512) {
        float p = fp[i];
        float d2 = __uint_as_float(g_minfwd[i]);
        fwd += (double)(p * sqrtf(d2));
        pen += (double)(1.0f - p);
    }
    for (int b = tid; b < REV_BLOCKS; b += 512) rev += g_part[b];

    double totF, totP, totR;
    red[tid] = fwd; __syncthreads();
    for (int o = 256; o > 0; o >>= 1) { if (tid < o) red[tid] += red[tid + o]; __syncthreads(); }
    totF = red[0]; __syncthreads();
    red[tid] = pen; __syncthreads();
    for (int o = 256; o > 0; o >>= 1) { if (tid < o) red[tid] += red[tid + o]; __syncthreads(); }
    totP = red[0]; __syncthreads();
    red[tid] = rev; __syncthreads();
    for (int o = 256; o > 0; o >>= 1) { if (tid < o) red[tid] += red[tid + o]; __syncthreads(); }
    totR = red[0];

    if (tid == 0) {
        double maxd = (double)__uint_as_float(g_maxbits);
        double result = totF + 1e-4 * totP + totR / (maxd + 1e-8) * 0.1;
        out[0] = (float)result;
    }
}

// ---------------- launch ----------------
extern "C" void kernel_launch(void* const* d_in, const int* in_sizes, int n_in,
                              void* d_out, int out_size) {
    const float* ov = (const float*)d_in[0];
    const int*   of = (const int*)  d_in[1];
    const float* sv = (const float*)d_in[2];
    const int*   sf = (const int*)  d_in[3];
    const float* fp = (const float*)d_in[4];
    float* out = (float*)d_out;

    init_kernel<<<(NCELLS + 255) / 256, 256>>>();
    prep_kernel<<<(N_OF + 255) / 256, 256>>>(ov, of, sv, sf);
    gen_samples_kernel<<<(N_SAMPLES + 255) / 256, 256>>>(sv, sf);

    // grid build
    count_kernel<<<(N_OV + 255) / 256, 256>>>(ov);
    scan1_kernel<<<SCAN_BLOCKS, 1024>>>();
    scan2_kernel<<<1, SCAN_BLOCKS>>>();
    scan3_kernel<<<(NCELLS + 255) / 256, 256>>>();
    scatter_kernel<<<(N_OV + 255) / 256, 256>>>(ov);

    // forward term (brute force)
    {
        dim3 grid((N_SF + 127) / 128, N_OF / FWD_CHUNK);
        forward_kernel<<<grid, 128>>>();
    }

    // reverse term: grid-accelerated exact 1-NN + fused reductions
    reverse_grid_kernel<<<REV_BLOCKS, 256>>>(fp);
    final_kernel<<<1, 512>>>(fp, out);
}